// round 1
// baseline (speedup 1.0000x reference)
#include <cuda_runtime.h>
#include <math.h>

// Problem constants
#define BB   2
#define TT   2048
#define CC   1024
#define HH   16
#define HD   64
#define HD2  32
#define MROWS (BB*TT)          // 4096
#define QKVW (3*CC)            // 3072

// Scratch (allocation-free rule: __device__ globals)
__device__ float g_qkv[(size_t)MROWS * QKVW];   // [B*T, 3C]
__device__ float g_att[(size_t)MROWS * CC];     // attention output [B*T, C]

// ---------------------------------------------------------------------------
// SGEMM: C[M,N] = A[M,K] @ B[K,N] + bias[N]
// BM=128, BN=128, BK=8, 256 threads, 8x8 register tile per thread.
// All dims divisible by tile sizes for this problem (no bounds checks).
// ---------------------------------------------------------------------------
__global__ __launch_bounds__(256) void sgemm_bias(
    const float* __restrict__ A, const float* __restrict__ Bm,
    const float* __restrict__ bias, float* __restrict__ Cm,
    int M, int N, int K)
{
    const int BM = 128, BN = 128, BK = 8, TM = 8, TN = 8;
    __shared__ float As[BK][BM];   // A tile transposed
    __shared__ float Bs[BK][BN];

    const int tid  = threadIdx.x;
    const int row0 = blockIdx.y * BM;
    const int col0 = blockIdx.x * BN;

    const int aRow = tid / (BK / 4);          // 0..127
    const int aCol = (tid % (BK / 4)) * 4;    // 0 or 4
    const int bRow = tid / (BN / 4);          // 0..7
    const int bCol = (tid % (BN / 4)) * 4;    // 0..124

    const int tr = tid / (BN / TN);           // 0..15
    const int tc = tid % (BN / TN);           // 0..15

    float acc[TM][TN];
    #pragma unroll
    for (int i = 0; i < TM; i++)
        #pragma unroll
        for (int j = 0; j < TN; j++) acc[i][j] = 0.f;

    const float* Aptr = A + (size_t)row0 * K;
    const float* Bptr = Bm + col0;

    for (int k0 = 0; k0 < K; k0 += BK) {
        float4 a4 = *(const float4*)(Aptr + (size_t)aRow * K + k0 + aCol);
        As[aCol + 0][aRow] = a4.x;
        As[aCol + 1][aRow] = a4.y;
        As[aCol + 2][aRow] = a4.z;
        As[aCol + 3][aRow] = a4.w;
        float4 b4 = *(const float4*)(Bptr + (size_t)(k0 + bRow) * N + bCol);
        *(float4*)&Bs[bRow][bCol] = b4;
        __syncthreads();

        #pragma unroll
        for (int kk = 0; kk < BK; ++kk) {
            float4 a0 = *(const float4*)&As[kk][tr * TM];
            float4 a1 = *(const float4*)&As[kk][tr * TM + 4];
            float4 b0 = *(const float4*)&Bs[kk][tc * TN];
            float4 b1 = *(const float4*)&Bs[kk][tc * TN + 4];
            float ra[TM] = {a0.x,a0.y,a0.z,a0.w,a1.x,a1.y,a1.z,a1.w};
            float rb[TN] = {b0.x,b0.y,b0.z,b0.w,b1.x,b1.y,b1.z,b1.w};
            #pragma unroll
            for (int i = 0; i < TM; i++)
                #pragma unroll
                for (int j = 0; j < TN; j++)
                    acc[i][j] += ra[i] * rb[j];
        }
        __syncthreads();
    }

    #pragma unroll
    for (int i = 0; i < TM; i++) {
        int r = row0 + tr * TM + i;
        #pragma unroll
        for (int j = 0; j < TN; j += 4) {
            int c = col0 + tc * TN + j;
            float4 o;
            o.x = acc[i][j + 0] + bias[c + 0];
            o.y = acc[i][j + 1] + bias[c + 1];
            o.z = acc[i][j + 2] + bias[c + 2];
            o.w = acc[i][j + 3] + bias[c + 3];
            *(float4*)(Cm + (size_t)r * N + c) = o;
        }
    }
}

// ---------------------------------------------------------------------------
// RoPE applied in-place to q and k halves of g_qkv.
// grid = B*T blocks, block = H*HD2 = 512 threads. Thread (h,d) updates the
// rotation pair (d, d+HD2) of head h for both q and k.
// ---------------------------------------------------------------------------
__global__ __launch_bounds__(512) void rope_kernel(
    float* __restrict__ qkv,
    const float* __restrict__ cosf, const float* __restrict__ sinf)
{
    const int bt  = blockIdx.x;        // 0..4095
    const int t   = bt % TT;
    const int tid = threadIdx.x;       // 0..511
    const int h   = tid / HD2;
    const int d   = tid % HD2;

    const float c = cosf[t * HD2 + d];
    const float s = sinf[t * HD2 + d];

    float* base = qkv + (size_t)bt * QKVW;
    float* q = base + h * HD;
    float q1 = q[d], q2 = q[d + HD2];
    q[d]       = q1 * c - q2 * s;
    q[d + HD2] = q1 * s + q2 * c;

    float* k = base + CC + h * HD;
    float k1 = k[d], k2 = k[d + HD2];
    k[d]       = k1 * c - k2 * s;
    k[d + HD2] = k1 * s + k2 * c;
}

// ---------------------------------------------------------------------------
// Flash attention (fp32, causal). One block = 64 query rows of one (b,h).
// grid = (T/64, B*H) = (32, 32). 256 threads as 16x16, each owning a 4x4
// micro-tile of the 64x64 score tile and a 4x4 slice of the 64-wide output.
// Smem: Qs[64][64] + KP[64][65] (K^T, buffer reused for P) + Vs[64][64]
// = 49408 bytes dynamic smem.
// ---------------------------------------------------------------------------
__global__ __launch_bounds__(256) void attn_kernel(
    const float* __restrict__ qkv, float* __restrict__ out)
{
    extern __shared__ float sm[];
    float* Qs = sm;                  // [64][64]
    float* KP = sm + 64 * 64;        // [64][65]  K^T then P
    float* Vs = KP + 64 * 65;        // [64][64]

    const int iTile = blockIdx.x;    // query tile
    const int bh    = blockIdx.y;
    const int b = bh / HH, h = bh % HH;
    const int tid = threadIdx.x;
    const int tr = tid >> 4;         // 0..15
    const int tc = tid & 15;         // 0..15
    const int i0 = iTile * 64;

    const float* qBase = qkv + (size_t)(b * TT) * QKVW + h * HD;
    const float* kBase = qBase + CC;
    const float* vBase = qBase + 2 * CC;

    // Load Q tile, pre-scaled by 1/sqrt(HD)
    #pragma unroll
    for (int it = 0; it < 4; ++it) {
        int idx = it * 256 + tid;    // 0..1023
        int r   = idx >> 4;
        int c4  = (idx & 15) << 2;
        float4 v = *(const float4*)(qBase + (size_t)(i0 + r) * QKVW + c4);
        v.x *= 0.125f; v.y *= 0.125f; v.z *= 0.125f; v.w *= 0.125f;
        *(float4*)&Qs[r * 64 + c4] = v;
    }

    float m[4], l[4], o[4][4];
    #pragma unroll
    for (int i = 0; i < 4; i++) {
        m[i] = -INFINITY; l[i] = 0.f;
        #pragma unroll
        for (int j = 0; j < 4; j++) o[i][j] = 0.f;
    }

    for (int jT = 0; jT <= iTile; ++jT) {
        const int j0 = jT * 64;
        __syncthreads();   // previous tile's KP/Vs fully consumed; Q visible (1st iter)

        // Load K (transposed into KP) and V
        #pragma unroll
        for (int it = 0; it < 4; ++it) {
            int idx = it * 256 + tid;
            int r   = idx >> 4;
            int c4  = (idx & 15) << 2;
            float4 kv = *(const float4*)(kBase + (size_t)(j0 + r) * QKVW + c4);
            KP[(c4 + 0) * 65 + r] = kv.x;
            KP[(c4 + 1) * 65 + r] = kv.y;
            KP[(c4 + 2) * 65 + r] = kv.z;
            KP[(c4 + 3) * 65 + r] = kv.w;
            float4 vv = *(const float4*)(vBase + (size_t)(j0 + r) * QKVW + c4);
            *(float4*)&Vs[r * 64 + c4] = vv;
        }
        __syncthreads();

        // S = (Q/sqrt(d)) K^T  — 4x4 per thread
        float s[4][4];
        #pragma unroll
        for (int i = 0; i < 4; i++)
            #pragma unroll
            for (int j = 0; j < 4; j++) s[i][j] = 0.f;

        #pragma unroll 4
        for (int d = 0; d < 64; ++d) {
            float qa[4], kb[4];
            #pragma unroll
            for (int i = 0; i < 4; i++) qa[i] = Qs[(tr * 4 + i) * 64 + d];
            #pragma unroll
            for (int j = 0; j < 4; j++) kb[j] = KP[d * 65 + tc * 4 + j];
            #pragma unroll
            for (int i = 0; i < 4; i++)
                #pragma unroll
                for (int j = 0; j < 4; j++)
                    s[i][j] += qa[i] * kb[j];
        }

        // Causal mask on the diagonal tile
        if (jT == iTile) {
            #pragma unroll
            for (int i = 0; i < 4; i++)
                #pragma unroll
                for (int j = 0; j < 4; j++)
                    if (j0 + tc * 4 + j > i0 + tr * 4 + i) s[i][j] = -INFINITY;
        }

        __syncthreads();   // all threads done reading K from KP; safe to overwrite with P

        // Online softmax per row (stats replicated across the 16 lanes of a row group)
        #pragma unroll
        for (int i = 0; i < 4; i++) {
            float mt = fmaxf(fmaxf(s[i][0], s[i][1]), fmaxf(s[i][2], s[i][3]));
            #pragma unroll
            for (int off = 8; off >= 1; off >>= 1)
                mt = fmaxf(mt, __shfl_xor_sync(0xffffffffu, mt, off, 16));
            float mnew  = fmaxf(m[i], mt);
            float alpha = __expf(m[i] - mnew);
            float p[4], ls = 0.f;
            #pragma unroll
            for (int j = 0; j < 4; j++) { p[j] = __expf(s[i][j] - mnew); ls += p[j]; }
            #pragma unroll
            for (int off = 8; off >= 1; off >>= 1)
                ls += __shfl_xor_sync(0xffffffffu, ls, off, 16);
            m[i] = mnew;
            l[i] = l[i] * alpha + ls;
            #pragma unroll
            for (int j = 0; j < 4; j++) o[i][j] *= alpha;
            #pragma unroll
            for (int j = 0; j < 4; j++)
                KP[(tr * 4 + i) * 65 + tc * 4 + j] = p[j];
        }
        __syncthreads();   // P visible to all

        // O += P @ V   (each thread: 4 rows x 4 cols of HD)
        #pragma unroll 2
        for (int k = 0; k < 64; ++k) {
            float4 v4 = *(const float4*)&Vs[k * 64 + tc * 4];
            float pv[4];
            #pragma unroll
            for (int i = 0; i < 4; i++) pv[i] = KP[(tr * 4 + i) * 65 + k];
            #pragma unroll
            for (int i = 0; i < 4; i++) {
                o[i][0] += pv[i] * v4.x;
                o[i][1] += pv[i] * v4.y;
                o[i][2] += pv[i] * v4.z;
                o[i][3] += pv[i] * v4.w;
            }
        }
    }

    // Normalize and store
    #pragma unroll
    for (int i = 0; i < 4; i++) {
        int r = i0 + tr * 4 + i;
        float inv = 1.f / l[i];
        float4 ov;
        ov.x = o[i][0] * inv; ov.y = o[i][1] * inv;
        ov.z = o[i][2] * inv; ov.w = o[i][3] * inv;
        *(float4*)(out + (size_t)(b * TT + r) * CC + h * HD + tc * 4) = ov;
    }
}

// ---------------------------------------------------------------------------
// Launch
// ---------------------------------------------------------------------------
extern "C" void kernel_launch(void* const* d_in, const int* in_sizes, int n_in,
                              void* d_out, int out_size)
{
    const float* x     = (const float*)d_in[0];
    const float* fcos  = (const float*)d_in[1];
    const float* fsin  = (const float*)d_in[2];
    const float* Wqkv  = (const float*)d_in[3];
    const float* bqkv  = (const float*)d_in[4];
    const float* Wproj = (const float*)d_in[5];
    const float* bproj = (const float*)d_in[6];
    float* out = (float*)d_out;

    float *qkv, *att;
    cudaGetSymbolAddress((void**)&qkv, g_qkv);
    cudaGetSymbolAddress((void**)&att, g_att);

    const int attSmem = (64 * 64 + 64 * 65 + 64 * 64) * (int)sizeof(float); // 49408
    cudaFuncSetAttribute(attn_kernel, cudaFuncAttributeMaxDynamicSharedMemorySize, attSmem);

    // 1) QKV = X @ Wqkv + bqkv     [4096,1024]x[1024,3072]
    {
        dim3 grid(QKVW / 128, MROWS / 128);   // (24, 32)
        sgemm_bias<<<grid, 256>>>(x, Wqkv, bqkv, qkv, MROWS, QKVW, CC);
    }
    // 2) RoPE in-place on q,k
    rope_kernel<<<MROWS, HH * HD2>>>(qkv, fcos, fsin);

    // 3) Causal flash attention -> g_att
    {
        dim3 grid(TT / 64, BB * HH);          // (32, 32)
        attn_kernel<<<grid, 256, attSmem>>>(qkv, att);
    }
    // 4) out = att @ Wproj + bproj  [4096,1024]x[1024,1024]
    {
        dim3 grid(CC / 128, MROWS / 128);     // (8, 32)
        sgemm_bias<<<grid, 256>>>(att, Wproj, bproj, out, MROWS, CC, CC);
    }
}

// round 2
// speedup vs baseline: 1.5291x; 1.5291x over previous
#include <cuda_runtime.h>
#include <cuda_bf16.h>
#include <math.h>

// Problem constants
#define BB   2
#define TT   2048
#define CC   1024
#define HH   16
#define HD   64
#define HD2  32
#define MROWS (BB*TT)          // 4096
#define QKVW (3*CC)            // 3072

// Scratch (allocation-free rule: __device__ globals)
__device__ float g_qkv[(size_t)MROWS * QKVW];   // [B*T, 3C]
__device__ float g_att[(size_t)MROWS * CC];     // attention output [B*T, C]

// ---------------------------------------------------------------------------
// Tensor-core GEMM with split-bf16 fp32 emulation:
//   C = A@B + bias,  A[M,K] fp32, B[K,N] fp32.
//   A = Ah + Al, B = Bh + Bl (bf16 hi + bf16 residual);
//   C ≈ Ah*Bh + Ah*Bl + Al*Bh  (Al*Bl term ~2^-16 relative, dropped)
// CTA tile 128x128x16, 256 threads (8 warps as 2x4, warp tile 64x32),
// mma.sync.m16n8k16 bf16, double-buffered smem, register-staged loads.
// Requires M%128==0, N%128==0, K%16==0 (true for both call sites).
// ---------------------------------------------------------------------------

__device__ __forceinline__ void split2(float x, float y, unsigned &h, unsigned &l)
{
    __nv_bfloat16 hx = __float2bfloat16(x), hy = __float2bfloat16(y);
    float rx = x - __bfloat162float(hx);
    float ry = y - __bfloat162float(hy);
    __nv_bfloat16 lx = __float2bfloat16(rx), ly = __float2bfloat16(ry);
    h = (unsigned)*(unsigned short*)&hx | ((unsigned)*(unsigned short*)&hy << 16);
    l = (unsigned)*(unsigned short*)&lx | ((unsigned)*(unsigned short*)&ly << 16);
}

__device__ __forceinline__ void ldsm_x4(unsigned r[4], unsigned addr)
{
    asm volatile("ldmatrix.sync.aligned.m8n8.x4.shared.b16 {%0,%1,%2,%3}, [%4];"
                 : "=r"(r[0]), "=r"(r[1]), "=r"(r[2]), "=r"(r[3]) : "r"(addr));
}

__device__ __forceinline__ void ldsm_x2_t(unsigned r[2], unsigned addr)
{
    asm volatile("ldmatrix.sync.aligned.m8n8.x2.trans.shared.b16 {%0,%1}, [%2];"
                 : "=r"(r[0]), "=r"(r[1]) : "r"(addr));
}

__device__ __forceinline__ void mma_bf16(float d[4], const unsigned a[4], const unsigned b[2])
{
    asm volatile("mma.sync.aligned.m16n8k16.row.col.f32.bf16.bf16.f32 "
                 "{%0,%1,%2,%3}, {%4,%5,%6,%7}, {%8,%9}, {%0,%1,%2,%3};"
                 : "+f"(d[0]), "+f"(d[1]), "+f"(d[2]), "+f"(d[3])
                 : "r"(a[0]), "r"(a[1]), "r"(a[2]), "r"(a[3]), "r"(b[0]), "r"(b[1]));
}

// Smem strides (in bf16 elements)
#define ASTR 24          // 48 bytes/row: ldmatrix conflict-free
#define BSTR 136         // 272 bytes/row: ldmatrix conflict-free
#define A_ELE (128*ASTR) // per-buffer elements
#define B_ELE (16*BSTR)

__global__ __launch_bounds__(256) void bgemm_bias(
    const float* __restrict__ A, const float* __restrict__ Bm,
    const float* __restrict__ bias, float* __restrict__ Cm,
    int M, int N, int K)
{
    __shared__ __align__(16) __nv_bfloat16 sAh[2][A_ELE];
    __shared__ __align__(16) __nv_bfloat16 sAl[2][A_ELE];
    __shared__ __align__(16) __nv_bfloat16 sBh[2][B_ELE];
    __shared__ __align__(16) __nv_bfloat16 sBl[2][B_ELE];

    const int tid  = threadIdx.x;
    const int lane = tid & 31;
    const int wid  = tid >> 5;          // 0..7
    const int wm   = wid >> 2;          // 0..1  (m)
    const int wn   = wid & 3;           // 0..3  (n)
    const int row0 = blockIdx.y * 128;
    const int col0 = blockIdx.x * 128;

    // gmem load mapping
    const int arow  = tid >> 1;               // 0..127
    const int acol0 = (tid & 1) * 8;          // 0 or 8
    const int brow  = tid >> 4;               // 0..15
    const int bcol0 = (tid & 15) * 8;         // 0..120

    const float* Aptr = A + (size_t)(row0 + arow) * K + acol0;
    const float* Bptr = Bm + col0 + bcol0;

    // shared base addresses (bytes, shared window)
    const unsigned bAh = (unsigned)__cvta_generic_to_shared(sAh);
    const unsigned bAl = (unsigned)__cvta_generic_to_shared(sAl);
    const unsigned bBh = (unsigned)__cvta_generic_to_shared(sBh);
    const unsigned bBl = (unsigned)__cvta_generic_to_shared(sBl);

    // per-lane ldmatrix offsets
    const unsigned aoff = (unsigned)((wm * 64 + (lane & 15)) * (ASTR * 2) + (lane >> 4) * 16);
    const unsigned boff = (unsigned)((lane & 15) * (BSTR * 2) + (wn * 32) * 2);

    float acc[4][4][4];
    #pragma unroll
    for (int mi = 0; mi < 4; mi++)
        #pragma unroll
        for (int ni = 0; ni < 4; ni++)
            #pragma unroll
            for (int r = 0; r < 4; r++) acc[mi][ni][r] = 0.f;

    const int KT = K >> 4;

    float4 a0, a1, b0, b1;   // stage registers

    // prologue: load tile 0, convert+store to buf 0
    a0 = *(const float4*)(Aptr + 0);
    a1 = *(const float4*)(Aptr + 4);
    b0 = *(const float4*)(Bptr + (size_t)brow * N + 0);
    b1 = *(const float4*)(Bptr + (size_t)brow * N + 4);
    {
        unsigned h[4], l[4];
        split2(a0.x, a0.y, h[0], l[0]); split2(a0.z, a0.w, h[1], l[1]);
        split2(a1.x, a1.y, h[2], l[2]); split2(a1.z, a1.w, h[3], l[3]);
        *(uint4*)&sAh[0][arow * ASTR + acol0] = make_uint4(h[0], h[1], h[2], h[3]);
        *(uint4*)&sAl[0][arow * ASTR + acol0] = make_uint4(l[0], l[1], l[2], l[3]);
        split2(b0.x, b0.y, h[0], l[0]); split2(b0.z, b0.w, h[1], l[1]);
        split2(b1.x, b1.y, h[2], l[2]); split2(b1.z, b1.w, h[3], l[3]);
        *(uint4*)&sBh[0][brow * BSTR + bcol0] = make_uint4(h[0], h[1], h[2], h[3]);
        *(uint4*)&sBl[0][brow * BSTR + bcol0] = make_uint4(l[0], l[1], l[2], l[3]);
    }
    __syncthreads();

    for (int kt = 0; kt < KT; ++kt) {
        const int buf = kt & 1;

        // issue gmem loads for next tile
        if (kt + 1 < KT) {
            const float* Ap = Aptr + (kt + 1) * 16;
            const float* Bp = Bptr + (size_t)((kt + 1) * 16 + brow) * N;
            a0 = *(const float4*)(Ap + 0);
            a1 = *(const float4*)(Ap + 4);
            b0 = *(const float4*)(Bp + 0);
            b1 = *(const float4*)(Bp + 4);
        }

        // compute from smem buf
        {
            const unsigned offA = (unsigned)(buf * A_ELE * 2);
            const unsigned offB = (unsigned)(buf * B_ELE * 2);
            unsigned ah[4][4], al[4][4], bh[4][2], bl[4][2];
            #pragma unroll
            for (int mi = 0; mi < 4; mi++) {
                ldsm_x4(ah[mi], bAh + offA + aoff + mi * 16 * (ASTR * 2));
                ldsm_x4(al[mi], bAl + offA + aoff + mi * 16 * (ASTR * 2));
            }
            #pragma unroll
            for (int ni = 0; ni < 4; ni++) {
                ldsm_x2_t(bh[ni], bBh + offB + boff + ni * 16);
                ldsm_x2_t(bl[ni], bBl + offB + boff + ni * 16);
            }
            #pragma unroll
            for (int mi = 0; mi < 4; mi++)
                #pragma unroll
                for (int ni = 0; ni < 4; ni++) {
                    mma_bf16(acc[mi][ni], ah[mi], bh[ni]);
                    mma_bf16(acc[mi][ni], ah[mi], bl[ni]);
                    mma_bf16(acc[mi][ni], al[mi], bh[ni]);
                }
        }

        // convert+store next tile into the other buffer
        if (kt + 1 < KT) {
            const int nb = buf ^ 1;
            unsigned h[4], l[4];
            split2(a0.x, a0.y, h[0], l[0]); split2(a0.z, a0.w, h[1], l[1]);
            split2(a1.x, a1.y, h[2], l[2]); split2(a1.z, a1.w, h[3], l[3]);
            *(uint4*)&sAh[nb][arow * ASTR + acol0] = make_uint4(h[0], h[1], h[2], h[3]);
            *(uint4*)&sAl[nb][arow * ASTR + acol0] = make_uint4(l[0], l[1], l[2], l[3]);
            split2(b0.x, b0.y, h[0], l[0]); split2(b0.z, b0.w, h[1], l[1]);
            split2(b1.x, b1.y, h[2], l[2]); split2(b1.z, b1.w, h[3], l[3]);
            *(uint4*)&sBh[nb][brow * BSTR + bcol0] = make_uint4(h[0], h[1], h[2], h[3]);
            *(uint4*)&sBl[nb][brow * BSTR + bcol0] = make_uint4(l[0], l[1], l[2], l[3]);
        }
        __syncthreads();
    }

    // epilogue: acc fragment layout: c0,c1 -> (row g, col 2t,2t+1); c2,c3 -> row g+8
    const int g = lane >> 2;
    const int tq = lane & 3;
    #pragma unroll
    for (int mi = 0; mi < 4; mi++) {
        const int r0 = row0 + wm * 64 + mi * 16 + g;
        #pragma unroll
        for (int ni = 0; ni < 4; ni++) {
            const int c = col0 + wn * 32 + ni * 8 + tq * 2;
            const float bz0 = bias[c], bz1 = bias[c + 1];
            float2 v0 = make_float2(acc[mi][ni][0] + bz0, acc[mi][ni][1] + bz1);
            float2 v1 = make_float2(acc[mi][ni][2] + bz0, acc[mi][ni][3] + bz1);
            *(float2*)(Cm + (size_t)r0 * N + c)       = v0;
            *(float2*)(Cm + (size_t)(r0 + 8) * N + c) = v1;
        }
    }
}

// ---------------------------------------------------------------------------
// RoPE applied in-place to q and k halves of g_qkv.
// ---------------------------------------------------------------------------
__global__ __launch_bounds__(512) void rope_kernel(
    float* __restrict__ qkv,
    const float* __restrict__ cosf, const float* __restrict__ sinf)
{
    const int bt  = blockIdx.x;        // 0..4095
    const int t   = bt % TT;
    const int tid = threadIdx.x;       // 0..511
    const int h   = tid / HD2;
    const int d   = tid % HD2;

    const float c = cosf[t * HD2 + d];
    const float s = sinf[t * HD2 + d];

    float* base = qkv + (size_t)bt * QKVW;
    float* q = base + h * HD;
    float q1 = q[d], q2 = q[d + HD2];
    q[d]       = q1 * c - q2 * s;
    q[d + HD2] = q1 * s + q2 * c;

    float* k = base + CC + h * HD;
    float k1 = k[d], k2 = k[d + HD2];
    k[d]       = k1 * c - k2 * s;
    k[d + HD2] = k1 * s + k2 * c;
}

// ---------------------------------------------------------------------------
// Flash attention (fp32, causal). One block = 64 query rows of one (b,h).
// ---------------------------------------------------------------------------
__global__ __launch_bounds__(256) void attn_kernel(
    const float* __restrict__ qkv, float* __restrict__ out)
{
    extern __shared__ float sm[];
    float* Qs = sm;                  // [64][64]
    float* KP = sm + 64 * 64;        // [64][65]  K^T then P
    float* Vs = KP + 64 * 65;        // [64][64]

    const int iTile = blockIdx.x;    // query tile
    const int bh    = blockIdx.y;
    const int b = bh / HH, h = bh % HH;
    const int tid = threadIdx.x;
    const int tr = tid >> 4;         // 0..15
    const int tc = tid & 15;         // 0..15
    const int i0 = iTile * 64;

    const float* qBase = qkv + (size_t)(b * TT) * QKVW + h * HD;
    const float* kBase = qBase + CC;
    const float* vBase = qBase + 2 * CC;

    #pragma unroll
    for (int it = 0; it < 4; ++it) {
        int idx = it * 256 + tid;
        int r   = idx >> 4;
        int c4  = (idx & 15) << 2;
        float4 v = *(const float4*)(qBase + (size_t)(i0 + r) * QKVW + c4);
        v.x *= 0.125f; v.y *= 0.125f; v.z *= 0.125f; v.w *= 0.125f;
        *(float4*)&Qs[r * 64 + c4] = v;
    }

    float m[4], l[4], o[4][4];
    #pragma unroll
    for (int i = 0; i < 4; i++) {
        m[i] = -INFINITY; l[i] = 0.f;
        #pragma unroll
        for (int j = 0; j < 4; j++) o[i][j] = 0.f;
    }

    for (int jT = 0; jT <= iTile; ++jT) {
        const int j0 = jT * 64;
        __syncthreads();

        #pragma unroll
        for (int it = 0; it < 4; ++it) {
            int idx = it * 256 + tid;
            int r   = idx >> 4;
            int c4  = (idx & 15) << 2;
            float4 kv = *(const float4*)(kBase + (size_t)(j0 + r) * QKVW + c4);
            KP[(c4 + 0) * 65 + r] = kv.x;
            KP[(c4 + 1) * 65 + r] = kv.y;
            KP[(c4 + 2) * 65 + r] = kv.z;
            KP[(c4 + 3) * 65 + r] = kv.w;
            float4 vv = *(const float4*)(vBase + (size_t)(j0 + r) * QKVW + c4);
            *(float4*)&Vs[r * 64 + c4] = vv;
        }
        __syncthreads();

        float s[4][4];
        #pragma unroll
        for (int i = 0; i < 4; i++)
            #pragma unroll
            for (int j = 0; j < 4; j++) s[i][j] = 0.f;

        #pragma unroll 4
        for (int d = 0; d < 64; ++d) {
            float qa[4], kb[4];
            #pragma unroll
            for (int i = 0; i < 4; i++) qa[i] = Qs[(tr * 4 + i) * 64 + d];
            #pragma unroll
            for (int j = 0; j < 4; j++) kb[j] = KP[d * 65 + tc * 4 + j];
            #pragma unroll
            for (int i = 0; i < 4; i++)
                #pragma unroll
                for (int j = 0; j < 4; j++)
                    s[i][j] += qa[i] * kb[j];
        }

        if (jT == iTile) {
            #pragma unroll
            for (int i = 0; i < 4; i++)
                #pragma unroll
                for (int j = 0; j < 4; j++)
                    if (j0 + tc * 4 + j > i0 + tr * 4 + i) s[i][j] = -INFINITY;
        }

        __syncthreads();

        #pragma unroll
        for (int i = 0; i < 4; i++) {
            float mt = fmaxf(fmaxf(s[i][0], s[i][1]), fmaxf(s[i][2], s[i][3]));
            #pragma unroll
            for (int off = 8; off >= 1; off >>= 1)
                mt = fmaxf(mt, __shfl_xor_sync(0xffffffffu, mt, off, 16));
            float mnew  = fmaxf(m[i], mt);
            float alpha = __expf(m[i] - mnew);
            float p[4], ls = 0.f;
            #pragma unroll
            for (int j = 0; j < 4; j++) { p[j] = __expf(s[i][j] - mnew); ls += p[j]; }
            #pragma unroll
            for (int off = 8; off >= 1; off >>= 1)
                ls += __shfl_xor_sync(0xffffffffu, ls, off, 16);
            m[i] = mnew;
            l[i] = l[i] * alpha + ls;
            #pragma unroll
            for (int j = 0; j < 4; j++) o[i][j] *= alpha;
            #pragma unroll
            for (int j = 0; j < 4; j++)
                KP[(tr * 4 + i) * 65 + tc * 4 + j] = p[j];
        }
        __syncthreads();

        #pragma unroll 2
        for (int k = 0; k < 64; ++k) {
            float4 v4 = *(const float4*)&Vs[k * 64 + tc * 4];
            float pv[4];
            #pragma unroll
            for (int i = 0; i < 4; i++) pv[i] = KP[(tr * 4 + i) * 65 + k];
            #pragma unroll
            for (int i = 0; i < 4; i++) {
                o[i][0] += pv[i] * v4.x;
                o[i][1] += pv[i] * v4.y;
                o[i][2] += pv[i] * v4.z;
                o[i][3] += pv[i] * v4.w;
            }
        }
    }

    #pragma unroll
    for (int i = 0; i < 4; i++) {
        int r = i0 + tr * 4 + i;
        float inv = 1.f / l[i];
        float4 ov;
        ov.x = o[i][0] * inv; ov.y = o[i][1] * inv;
        ov.z = o[i][2] * inv; ov.w = o[i][3] * inv;
        *(float4*)(out + (size_t)(b * TT + r) * CC + h * HD + tc * 4) = ov;
    }
}

// ---------------------------------------------------------------------------
// Launch
// ---------------------------------------------------------------------------
extern "C" void kernel_launch(void* const* d_in, const int* in_sizes, int n_in,
                              void* d_out, int out_size)
{
    const float* x     = (const float*)d_in[0];
    const float* fcos  = (const float*)d_in[1];
    const float* fsin  = (const float*)d_in[2];
    const float* Wqkv  = (const float*)d_in[3];
    const float* bqkv  = (const float*)d_in[4];
    const float* Wproj = (const float*)d_in[5];
    const float* bproj = (const float*)d_in[6];
    float* out = (float*)d_out;

    float *qkv, *att;
    cudaGetSymbolAddress((void**)&qkv, g_qkv);
    cudaGetSymbolAddress((void**)&att, g_att);

    const int attSmem = (64 * 64 + 64 * 65 + 64 * 64) * (int)sizeof(float); // 49408
    cudaFuncSetAttribute(attn_kernel, cudaFuncAttributeMaxDynamicSharedMemorySize, attSmem);

    // 1) QKV = X @ Wqkv + bqkv     [4096,1024]x[1024,3072]  (tensor cores)
    {
        dim3 grid(QKVW / 128, MROWS / 128);   // (24, 32)
        bgemm_bias<<<grid, 256>>>(x, Wqkv, bqkv, qkv, MROWS, QKVW, CC);
    }
    // 2) RoPE in-place on q,k
    rope_kernel<<<MROWS, HH * HD2>>>(qkv, fcos, fsin);

    // 3) Causal flash attention -> g_att
    {
        dim3 grid(TT / 64, BB * HH);          // (32, 32)
        attn_kernel<<<grid, 256, attSmem>>>(qkv, att);
    }
    // 4) out = att @ Wproj + bproj  [4096,1024]x[1024,1024]  (tensor cores)
    {
        dim3 grid(CC / 128, MROWS / 128);     // (8, 32)
        bgemm_bias<<<grid, 256>>>(att, Wproj, bproj, out, MROWS, CC, CC);
    }
}

// round 3
// speedup vs baseline: 2.8060x; 1.8350x over previous
#include <cuda_runtime.h>
#include <cuda_bf16.h>
#include <math.h>

// Problem constants
#define BB   2
#define TT   2048
#define CC   1024
#define HH   16
#define HD   64
#define HD2  32
#define MROWS (BB*TT)          // 4096
#define QKVW (3*CC)            // 3072

// Scratch (allocation-free rule: __device__ globals)
__device__ float g_qkv[(size_t)MROWS * QKVW];   // [B*T, 3C]
__device__ float g_att[(size_t)MROWS * CC];     // attention output [B*T, C]
// Head-contiguous bf16 hi/lo splits of roped q, k and v: [b*H+h][T][64]
#define HELEMS ((size_t)BB * HH * TT * HD)
__device__ __nv_bfloat16 g_qh[HELEMS], g_ql[HELEMS];
__device__ __nv_bfloat16 g_kh[HELEMS], g_kl[HELEMS];
__device__ __nv_bfloat16 g_vh[HELEMS], g_vl[HELEMS];

// ---------------------------------------------------------------------------
// Common MMA helpers
// ---------------------------------------------------------------------------
__device__ __forceinline__ void split2(float x, float y, unsigned &h, unsigned &l)
{
    __nv_bfloat16 hx = __float2bfloat16(x), hy = __float2bfloat16(y);
    float rx = x - __bfloat162float(hx);
    float ry = y - __bfloat162float(hy);
    __nv_bfloat16 lx = __float2bfloat16(rx), ly = __float2bfloat16(ry);
    h = (unsigned)*(unsigned short*)&hx | ((unsigned)*(unsigned short*)&hy << 16);
    l = (unsigned)*(unsigned short*)&lx | ((unsigned)*(unsigned short*)&ly << 16);
}

__device__ __forceinline__ void ldsm_x4(unsigned r[4], unsigned addr)
{
    asm volatile("ldmatrix.sync.aligned.m8n8.x4.shared.b16 {%0,%1,%2,%3}, [%4];"
                 : "=r"(r[0]), "=r"(r[1]), "=r"(r[2]), "=r"(r[3]) : "r"(addr));
}

__device__ __forceinline__ void ldsm_x4_t(unsigned r[4], unsigned addr)
{
    asm volatile("ldmatrix.sync.aligned.m8n8.x4.trans.shared.b16 {%0,%1,%2,%3}, [%4];"
                 : "=r"(r[0]), "=r"(r[1]), "=r"(r[2]), "=r"(r[3]) : "r"(addr));
}

__device__ __forceinline__ void ldsm_x2_t(unsigned r[2], unsigned addr)
{
    asm volatile("ldmatrix.sync.aligned.m8n8.x2.trans.shared.b16 {%0,%1}, [%2];"
                 : "=r"(r[0]), "=r"(r[1]) : "r"(addr));
}

__device__ __forceinline__ void mma_bf16(float d[4], const unsigned a[4], unsigned b0, unsigned b1)
{
    asm volatile("mma.sync.aligned.m16n8k16.row.col.f32.bf16.bf16.f32 "
                 "{%0,%1,%2,%3}, {%4,%5,%6,%7}, {%8,%9}, {%0,%1,%2,%3};"
                 : "+f"(d[0]), "+f"(d[1]), "+f"(d[2]), "+f"(d[3])
                 : "r"(a[0]), "r"(a[1]), "r"(a[2]), "r"(a[3]), "r"(b0), "r"(b1));
}

// ---------------------------------------------------------------------------
// Split-bf16 tensor-core GEMM: C = A@B + bias (same as R2)
// ---------------------------------------------------------------------------
#define ASTR 24
#define BSTR 136
#define A_ELE (128*ASTR)
#define B_ELE (16*BSTR)

__global__ __launch_bounds__(256) void bgemm_bias(
    const float* __restrict__ A, const float* __restrict__ Bm,
    const float* __restrict__ bias, float* __restrict__ Cm,
    int M, int N, int K)
{
    __shared__ __align__(16) __nv_bfloat16 sAh[2][A_ELE];
    __shared__ __align__(16) __nv_bfloat16 sAl[2][A_ELE];
    __shared__ __align__(16) __nv_bfloat16 sBh[2][B_ELE];
    __shared__ __align__(16) __nv_bfloat16 sBl[2][B_ELE];

    const int tid  = threadIdx.x;
    const int lane = tid & 31;
    const int wid  = tid >> 5;
    const int wm   = wid >> 2;
    const int wn   = wid & 3;
    const int row0 = blockIdx.y * 128;
    const int col0 = blockIdx.x * 128;

    const int arow  = tid >> 1;
    const int acol0 = (tid & 1) * 8;
    const int brow  = tid >> 4;
    const int bcol0 = (tid & 15) * 8;

    const float* Aptr = A + (size_t)(row0 + arow) * K + acol0;
    const float* Bptr = Bm + col0 + bcol0;

    const unsigned bAh = (unsigned)__cvta_generic_to_shared(sAh);
    const unsigned bAl = (unsigned)__cvta_generic_to_shared(sAl);
    const unsigned bBh = (unsigned)__cvta_generic_to_shared(sBh);
    const unsigned bBl = (unsigned)__cvta_generic_to_shared(sBl);

    const unsigned aoff = (unsigned)((wm * 64 + (lane & 15)) * (ASTR * 2) + (lane >> 4) * 16);
    const unsigned boff = (unsigned)((lane & 15) * (BSTR * 2) + (wn * 32) * 2);

    float acc[4][4][4];
    #pragma unroll
    for (int mi = 0; mi < 4; mi++)
        #pragma unroll
        for (int ni = 0; ni < 4; ni++)
            #pragma unroll
            for (int r = 0; r < 4; r++) acc[mi][ni][r] = 0.f;

    const int KT = K >> 4;
    float4 a0, a1, b0, b1;

    a0 = *(const float4*)(Aptr + 0);
    a1 = *(const float4*)(Aptr + 4);
    b0 = *(const float4*)(Bptr + (size_t)brow * N + 0);
    b1 = *(const float4*)(Bptr + (size_t)brow * N + 4);
    {
        unsigned h[4], l[4];
        split2(a0.x, a0.y, h[0], l[0]); split2(a0.z, a0.w, h[1], l[1]);
        split2(a1.x, a1.y, h[2], l[2]); split2(a1.z, a1.w, h[3], l[3]);
        *(uint4*)&sAh[0][arow * ASTR + acol0] = make_uint4(h[0], h[1], h[2], h[3]);
        *(uint4*)&sAl[0][arow * ASTR + acol0] = make_uint4(l[0], l[1], l[2], l[3]);
        split2(b0.x, b0.y, h[0], l[0]); split2(b0.z, b0.w, h[1], l[1]);
        split2(b1.x, b1.y, h[2], l[2]); split2(b1.z, b1.w, h[3], l[3]);
        *(uint4*)&sBh[0][brow * BSTR + bcol0] = make_uint4(h[0], h[1], h[2], h[3]);
        *(uint4*)&sBl[0][brow * BSTR + bcol0] = make_uint4(l[0], l[1], l[2], l[3]);
    }
    __syncthreads();

    for (int kt = 0; kt < KT; ++kt) {
        const int buf = kt & 1;

        if (kt + 1 < KT) {
            const float* Ap = Aptr + (kt + 1) * 16;
            const float* Bp = Bptr + (size_t)((kt + 1) * 16 + brow) * N;
            a0 = *(const float4*)(Ap + 0);
            a1 = *(const float4*)(Ap + 4);
            b0 = *(const float4*)(Bp + 0);
            b1 = *(const float4*)(Bp + 4);
        }

        {
            const unsigned offA = (unsigned)(buf * A_ELE * 2);
            const unsigned offB = (unsigned)(buf * B_ELE * 2);
            unsigned ah[4][4], al[4][4], bh[4][4], bl[4][4];
            #pragma unroll
            for (int mi = 0; mi < 4; mi++) {
                ldsm_x4(ah[mi], bAh + offA + aoff + mi * 16 * (ASTR * 2));
                ldsm_x4(al[mi], bAl + offA + aoff + mi * 16 * (ASTR * 2));
            }
            #pragma unroll
            for (int ni = 0; ni < 4; ni++) {
                ldsm_x2_t(bh[ni], bBh + offB + boff + ni * 16);
                ldsm_x2_t(bl[ni], bBl + offB + boff + ni * 16);
            }
            #pragma unroll
            for (int mi = 0; mi < 4; mi++)
                #pragma unroll
                for (int ni = 0; ni < 4; ni++) {
                    mma_bf16(acc[mi][ni], ah[mi], bh[ni][0], bh[ni][1]);
                    mma_bf16(acc[mi][ni], ah[mi], bl[ni][0], bl[ni][1]);
                    mma_bf16(acc[mi][ni], al[mi], bh[ni][0], bh[ni][1]);
                }
        }

        if (kt + 1 < KT) {
            const int nb = buf ^ 1;
            unsigned h[4], l[4];
            split2(a0.x, a0.y, h[0], l[0]); split2(a0.z, a0.w, h[1], l[1]);
            split2(a1.x, a1.y, h[2], l[2]); split2(a1.z, a1.w, h[3], l[3]);
            *(uint4*)&sAh[nb][arow * ASTR + acol0] = make_uint4(h[0], h[1], h[2], h[3]);
            *(uint4*)&sAl[nb][arow * ASTR + acol0] = make_uint4(l[0], l[1], l[2], l[3]);
            split2(b0.x, b0.y, h[0], l[0]); split2(b0.z, b0.w, h[1], l[1]);
            split2(b1.x, b1.y, h[2], l[2]); split2(b1.z, b1.w, h[3], l[3]);
            *(uint4*)&sBh[nb][brow * BSTR + bcol0] = make_uint4(h[0], h[1], h[2], h[3]);
            *(uint4*)&sBl[nb][brow * BSTR + bcol0] = make_uint4(l[0], l[1], l[2], l[3]);
        }
        __syncthreads();
    }

    const int g = lane >> 2;
    const int tq = lane & 3;
    #pragma unroll
    for (int mi = 0; mi < 4; mi++) {
        const int r0 = row0 + wm * 64 + mi * 16 + g;
        #pragma unroll
        for (int ni = 0; ni < 4; ni++) {
            const int c = col0 + wn * 32 + ni * 8 + tq * 2;
            const float bz0 = bias[c], bz1 = bias[c + 1];
            float2 v0 = make_float2(acc[mi][ni][0] + bz0, acc[mi][ni][1] + bz1);
            float2 v1 = make_float2(acc[mi][ni][2] + bz0, acc[mi][ni][3] + bz1);
            *(float2*)(Cm + (size_t)r0 * N + c)       = v0;
            *(float2*)(Cm + (size_t)(r0 + 8) * N + c) = v1;
        }
    }
}

// ---------------------------------------------------------------------------
// RoPE + split to bf16 hi/lo, head-contiguous layout [b*H+h][T][64].
// Q pre-scaled by 1/sqrt(HD).
// ---------------------------------------------------------------------------
__device__ __forceinline__ void split1(float x, __nv_bfloat16 &h, __nv_bfloat16 &l)
{
    h = __float2bfloat16(x);
    l = __float2bfloat16(x - __bfloat162float(h));
}

__global__ __launch_bounds__(512) void rope_split(
    const float* __restrict__ qkv,
    const float* __restrict__ cosf, const float* __restrict__ sinf,
    __nv_bfloat16* __restrict__ qh, __nv_bfloat16* __restrict__ ql,
    __nv_bfloat16* __restrict__ kh, __nv_bfloat16* __restrict__ kl,
    __nv_bfloat16* __restrict__ vh, __nv_bfloat16* __restrict__ vl)
{
    const int bt  = blockIdx.x;
    const int b   = bt / TT;
    const int t   = bt % TT;
    const int tid = threadIdx.x;
    const int h   = tid >> 5;
    const int d   = tid & 31;

    const float c = cosf[t * HD2 + d];
    const float s = sinf[t * HD2 + d];

    const float* base = qkv + (size_t)bt * QKVW;
    const size_t dst = ((size_t)(b * HH + h) * TT + t) * HD + d;

    float q1 = base[h * HD + d], q2 = base[h * HD + d + HD2];
    float qr1 = (q1 * c - q2 * s) * 0.125f;
    float qr2 = (q1 * s + q2 * c) * 0.125f;
    split1(qr1, qh[dst], ql[dst]);
    split1(qr2, qh[dst + HD2], ql[dst + HD2]);

    float k1 = base[CC + h * HD + d], k2 = base[CC + h * HD + d + HD2];
    float kr1 = k1 * c - k2 * s;
    float kr2 = k1 * s + k2 * c;
    split1(kr1, kh[dst], kl[dst]);
    split1(kr2, kh[dst + HD2], kl[dst + HD2]);

    float v1 = base[2 * CC + h * HD + d], v2 = base[2 * CC + h * HD + d + HD2];
    split1(v1, vh[dst], vl[dst]);
    split1(v2, vh[dst + HD2], vl[dst + HD2]);
}

// ---------------------------------------------------------------------------
// Tensor-core flash attention (split-bf16, causal).
// Br=64 (4 warps x 16 rows), Bc=64. grid=(T/64, B*H), 128 threads.
// ---------------------------------------------------------------------------
#define KSTR  72          // smem row stride in bf16 elems (144B, ldmatrix conflict-free)
#define KSTR2 144

__global__ __launch_bounds__(128) void attn_mma(
    const __nv_bfloat16* __restrict__ qh_g, const __nv_bfloat16* __restrict__ ql_g,
    const __nv_bfloat16* __restrict__ kh_g, const __nv_bfloat16* __restrict__ kl_g,
    const __nv_bfloat16* __restrict__ vh_g, const __nv_bfloat16* __restrict__ vl_g,
    float* __restrict__ out)
{
    __shared__ __align__(16) __nv_bfloat16 sKh[64 * KSTR];
    __shared__ __align__(16) __nv_bfloat16 sKl[64 * KSTR];
    __shared__ __align__(16) __nv_bfloat16 sVh[64 * KSTR];
    __shared__ __align__(16) __nv_bfloat16 sVl[64 * KSTR];

    const int iTile = blockIdx.x;
    const int bh    = blockIdx.y;
    const int b = bh / HH, h = bh % HH;
    const int tid  = threadIdx.x;
    const int lane = tid & 31;
    const int wid  = tid >> 5;          // 0..3
    const int wr   = wid * 16;          // warp's first query row within tile
    const int i0   = iTile * 64;
    const int g    = lane >> 2;
    const int tq   = lane & 3;

    const size_t hoff = (size_t)bh * TT * HD;

    const unsigned bKh = (unsigned)__cvta_generic_to_shared(sKh);
    const unsigned bKl = (unsigned)__cvta_generic_to_shared(sKl);
    const unsigned bVh = (unsigned)__cvta_generic_to_shared(sVh);
    const unsigned bVl = (unsigned)__cvta_generic_to_shared(sVl);

    // ---- stage Q tile (hi/lo) through sKh/sKl, ldmatrix into registers ----
    {
        const uint4* qhp = (const uint4*)(qh_g + hoff + (size_t)i0 * HD);
        const uint4* qlp = (const uint4*)(ql_g + hoff + (size_t)i0 * HD);
        #pragma unroll
        for (int it = 0; it < 4; ++it) {
            int idx = it * 128 + tid;        // 0..511 -> 64 rows x 8 chunks
            int r = idx >> 3, c8 = (idx & 7) * 8;
            *(uint4*)&sKh[r * KSTR + c8] = qhp[idx];
            *(uint4*)&sKl[r * KSTR + c8] = qlp[idx];
        }
    }
    __syncthreads();

    unsigned qhf[4][4], qlf[4][4];
    {
        const unsigned aoffq = (unsigned)((wr + (lane & 15)) * KSTR2 + (lane >> 4) * 16);
        #pragma unroll
        for (int kc = 0; kc < 4; ++kc) {
            ldsm_x4(qhf[kc], bKh + aoffq + kc * 32);
            ldsm_x4(qlf[kc], bKl + aoffq + kc * 32);
        }
    }

    float m0 = -INFINITY, m1 = -INFINITY, l0 = 0.f, l1 = 0.f;
    float o[8][4];
    #pragma unroll
    for (int ni = 0; ni < 8; ni++)
        #pragma unroll
        for (int e = 0; e < 4; e++) o[ni][e] = 0.f;

    const uint4* khp = (const uint4*)(kh_g + hoff);
    const uint4* klp = (const uint4*)(kl_g + hoff);
    const uint4* vhp = (const uint4*)(vh_g + hoff);
    const uint4* vlp = (const uint4*)(vl_g + hoff);

    for (int jT = 0; jT <= iTile; ++jT) {
        const int j0 = jT * 64;
        __syncthreads();   // protect smem from previous iteration readers / Q staging

        // ---- load K/V hi+lo tiles (row r of tile = key j0+r) ----
        {
            const int base = j0 * 8;       // uint4 index of tile start
            #pragma unroll
            for (int it = 0; it < 4; ++it) {
                int idx = it * 128 + tid;
                int r = idx >> 3, c8 = (idx & 7) * 8;
                *(uint4*)&sKh[r * KSTR + c8] = khp[base + idx];
                *(uint4*)&sKl[r * KSTR + c8] = klp[base + idx];
                *(uint4*)&sVh[r * KSTR + c8] = vhp[base + idx];
                *(uint4*)&sVl[r * KSTR + c8] = vlp[base + idx];
            }
        }
        __syncthreads();

        // ---- S = Q K^T (split: Qh*Kh + Qh*Kl + Ql*Kh) ----
        float s[8][4];
        #pragma unroll
        for (int ni = 0; ni < 8; ni++)
            #pragma unroll
            for (int e = 0; e < 4; e++) s[ni][e] = 0.f;

        #pragma unroll
        for (int kc = 0; kc < 4; ++kc) {
            #pragma unroll
            for (int n2 = 0; n2 < 4; ++n2) {
                unsigned rh[4], rl[4];
                const unsigned ad = (unsigned)((n2 * 16 + (lane & 15)) * KSTR2
                                               + (lane >> 4) * 16 + kc * 32);
                ldsm_x4(rh, bKh + ad);
                ldsm_x4(rl, bKl + ad);
                // frag 2*n2: b = {r0, r2};  frag 2*n2+1: b = {r1, r3}
                mma_bf16(s[2 * n2],     qhf[kc], rh[0], rh[2]);
                mma_bf16(s[2 * n2],     qhf[kc], rl[0], rl[2]);
                mma_bf16(s[2 * n2],     qlf[kc], rh[0], rh[2]);
                mma_bf16(s[2 * n2 + 1], qhf[kc], rh[1], rh[3]);
                mma_bf16(s[2 * n2 + 1], qhf[kc], rl[1], rl[3]);
                mma_bf16(s[2 * n2 + 1], qlf[kc], rh[1], rh[3]);
            }
        }

        // ---- causal mask (diagonal tile only) ----
        if (jT == iTile) {
            const int row0 = i0 + wr + g, row1 = row0 + 8;
            #pragma unroll
            for (int ni = 0; ni < 8; ++ni) {
                const int c0 = j0 + ni * 8 + tq * 2;
                if (c0 > row0)     s[ni][0] = -INFINITY;
                if (c0 + 1 > row0) s[ni][1] = -INFINITY;
                if (c0 > row1)     s[ni][2] = -INFINITY;
                if (c0 + 1 > row1) s[ni][3] = -INFINITY;
            }
        }

        // ---- online softmax ----
        float rm0 = -INFINITY, rm1 = -INFINITY;
        #pragma unroll
        for (int ni = 0; ni < 8; ++ni) {
            rm0 = fmaxf(rm0, fmaxf(s[ni][0], s[ni][1]));
            rm1 = fmaxf(rm1, fmaxf(s[ni][2], s[ni][3]));
        }
        rm0 = fmaxf(rm0, __shfl_xor_sync(0xffffffffu, rm0, 1));
        rm0 = fmaxf(rm0, __shfl_xor_sync(0xffffffffu, rm0, 2));
        rm1 = fmaxf(rm1, __shfl_xor_sync(0xffffffffu, rm1, 1));
        rm1 = fmaxf(rm1, __shfl_xor_sync(0xffffffffu, rm1, 2));

        const float mn0 = fmaxf(m0, rm0), mn1 = fmaxf(m1, rm1);
        const float al0 = __expf(m0 - mn0), al1 = __expf(m1 - mn1);
        m0 = mn0; m1 = mn1;

        unsigned ph[8][2], pl[8][2];
        float sum0 = 0.f, sum1 = 0.f;
        #pragma unroll
        for (int ni = 0; ni < 8; ++ni) {
            float p0 = __expf(s[ni][0] - mn0);
            float p1 = __expf(s[ni][1] - mn0);
            float p2 = __expf(s[ni][2] - mn1);
            float p3 = __expf(s[ni][3] - mn1);
            sum0 += p0 + p1; sum1 += p2 + p3;
            split2(p0, p1, ph[ni][0], pl[ni][0]);
            split2(p2, p3, ph[ni][1], pl[ni][1]);
        }
        sum0 += __shfl_xor_sync(0xffffffffu, sum0, 1);
        sum0 += __shfl_xor_sync(0xffffffffu, sum0, 2);
        sum1 += __shfl_xor_sync(0xffffffffu, sum1, 1);
        sum1 += __shfl_xor_sync(0xffffffffu, sum1, 2);
        l0 = l0 * al0 + sum0;
        l1 = l1 * al1 + sum1;

        #pragma unroll
        for (int ni = 0; ni < 8; ++ni) {
            o[ni][0] *= al0; o[ni][1] *= al0;
            o[ni][2] *= al1; o[ni][3] *= al1;
        }

        // ---- O += P V (split: Ph*Vh + Ph*Vl + Pl*Vh) ----
        #pragma unroll
        for (int kc = 0; kc < 4; ++kc) {
            unsigned ah[4] = { ph[2 * kc][0], ph[2 * kc][1], ph[2 * kc + 1][0], ph[2 * kc + 1][1] };
            unsigned aml[4] = { pl[2 * kc][0], pl[2 * kc][1], pl[2 * kc + 1][0], pl[2 * kc + 1][1] };
            #pragma unroll
            for (int n2 = 0; n2 < 4; ++n2) {
                unsigned vh4[4], vl4[4];
                const unsigned ad = (unsigned)((kc * 16 + (lane & 15)) * KSTR2
                                               + (n2 * 2 + (lane >> 4)) * 16);
                ldsm_x4_t(vh4, bVh + ad);
                ldsm_x4_t(vl4, bVl + ad);
                // frag 2*n2: b = {r0, r1};  frag 2*n2+1: b = {r2, r3}
                mma_bf16(o[2 * n2],     ah,  vh4[0], vh4[1]);
                mma_bf16(o[2 * n2],     ah,  vl4[0], vl4[1]);
                mma_bf16(o[2 * n2],     aml, vh4[0], vh4[1]);
                mma_bf16(o[2 * n2 + 1], ah,  vh4[2], vh4[3]);
                mma_bf16(o[2 * n2 + 1], ah,  vl4[2], vl4[3]);
                mma_bf16(o[2 * n2 + 1], aml, vh4[2], vh4[3]);
            }
        }
    }

    // ---- normalize + store ----
    const float inv0 = 1.f / l0, inv1 = 1.f / l1;
    const int row0 = i0 + wr + g;
    #pragma unroll
    for (int ni = 0; ni < 8; ++ni) {
        const int col = h * HD + ni * 8 + tq * 2;
        *(float2*)(out + (size_t)(b * TT + row0) * CC + col) =
            make_float2(o[ni][0] * inv0, o[ni][1] * inv0);
        *(float2*)(out + (size_t)(b * TT + row0 + 8) * CC + col) =
            make_float2(o[ni][2] * inv1, o[ni][3] * inv1);
    }
}

// ---------------------------------------------------------------------------
// Launch
// ---------------------------------------------------------------------------
extern "C" void kernel_launch(void* const* d_in, const int* in_sizes, int n_in,
                              void* d_out, int out_size)
{
    const float* x     = (const float*)d_in[0];
    const float* fcos  = (const float*)d_in[1];
    const float* fsin  = (const float*)d_in[2];
    const float* Wqkv  = (const float*)d_in[3];
    const float* bqkv  = (const float*)d_in[4];
    const float* Wproj = (const float*)d_in[5];
    const float* bproj = (const float*)d_in[6];
    float* out = (float*)d_out;

    float *qkv, *att;
    __nv_bfloat16 *qh, *ql, *kh, *kl, *vh, *vl;
    cudaGetSymbolAddress((void**)&qkv, g_qkv);
    cudaGetSymbolAddress((void**)&att, g_att);
    cudaGetSymbolAddress((void**)&qh, g_qh);
    cudaGetSymbolAddress((void**)&ql, g_ql);
    cudaGetSymbolAddress((void**)&kh, g_kh);
    cudaGetSymbolAddress((void**)&kl, g_kl);
    cudaGetSymbolAddress((void**)&vh, g_vh);
    cudaGetSymbolAddress((void**)&vl, g_vl);

    // 1) QKV = X @ Wqkv + bqkv
    {
        dim3 grid(QKVW / 128, MROWS / 128);
        bgemm_bias<<<grid, 256>>>(x, Wqkv, bqkv, qkv, MROWS, QKVW, CC);
    }
    // 2) RoPE + bf16 hi/lo split into head-contiguous layout
    rope_split<<<MROWS, 512>>>(qkv, fcos, fsin, qh, ql, kh, kl, vh, vl);

    // 3) Tensor-core causal flash attention -> g_att
    {
        dim3 grid(TT / 64, BB * HH);
        attn_mma<<<grid, 128>>>(qh, ql, kh, kl, vh, vl, att);
    }
    // 4) out = att @ Wproj + bproj
    {
        dim3 grid(CC / 128, MROWS / 128);
        bgemm_bias<<<grid, 256>>>(att, Wproj, bproj, out, MROWS, CC, CC);
    }
}